// round 4
// baseline (speedup 1.0000x reference)
#include <cuda_runtime.h>

// Fused bleed-correction kernel.
// out[i] = src[i] - sum_{j in {i-1,i+1} & valid} [ conv3x3(src[j], kA_ij)
//                                               + conv3x3(cbrt(src[j]*src[i]^2), kB_ij) ]
// conv = cross-correlation (JAX conv_general_dilated, no flip), SAME zero pad.
//
// Tiling: one block = 128x32 output pixels of one (channel, image).
// smem: src tile + halo, nb tile + halo. The inter-term is elementwise, so it is
// computed IN PLACE over the nb tile between the two conv passes (2 arrays only).
// Each thread computes a 4x4 register strip; per input row it does one aligned
// LDS.128 + LDS.64 (6 floats feed all 12 horizontal taps x 3 output rows),
// keeping shared-memory crossbar traffic ~4x below the naive 9-tap gather.

namespace {

constexpr int Hh = 512, Ww = 512;
constexpr int TW = 128, TH = 32;
constexpr int SCOLS = TW + 2;   // 130 logical cols (with halo)
constexpr int SROWS = TH + 2;   // 34 rows
constexpr int SW_   = 132;      // padded row stride: 132*4B = 528B, multiple of 16
constexpr int NTHREADS = 256;

__device__ __forceinline__ float fast_cbrt_nonneg(float x) {
    // x >= 0. exp2(log2(x)/3). __logf(0)=-inf -> exp2(-inf)=0, matches zero pad.
    return __powf(x, 0.3333333333333333f);
}

__device__ __forceinline__ void conv_accum(const float* __restrict__ s,
                                           const float kk[9],
                                           float acc[4][4],
                                           int oyb, int lx) {
    // Thread's outputs: local rows oyb..oyb+3, local cols lx..lx+3.
    // Input rows needed: logical oyb-1..oyb+4 -> physical oyb..oyb+5 (halo off +1).
    // Input cols needed: logical lx-1..lx+4 -> physical lx..lx+5.
    #pragma unroll
    for (int iy = 0; iy < 6; iy++) {
        const float* row = s + (oyb + iy) * SW_ + lx;   // 16B aligned
        float4 v0 = *reinterpret_cast<const float4*>(row);
        float2 v1 = *reinterpret_cast<const float2*>(row + 4);
        float v[6] = {v0.x, v0.y, v0.z, v0.w, v1.x, v1.y};
        const int ir = iy - 1;  // input row relative to thread's output base
        #pragma unroll
        for (int o = 0; o < 4; o++) {
            const int kr = ir - o + 1;   // kernel row index for this (input,output) pair
            if (kr >= 0 && kr < 3) {
                #pragma unroll
                for (int c = 0; c < 4; c++) {
                    acc[o][c] = fmaf(kk[kr * 3 + 0], v[c + 0],
                                fmaf(kk[kr * 3 + 1], v[c + 1],
                                fmaf(kk[kr * 3 + 2], v[c + 2], acc[o][c])));
                }
            }
        }
    }
}

__global__ __launch_bounds__(NTHREADS)
void bleed_kernel(const float* __restrict__ sources,
                  const float* __restrict__ kernels,
                  float* __restrict__ out)
{
    __shared__ __align__(16) float s_src[SROWS * SW_];
    __shared__ __align__(16) float s_nb [SROWS * SW_];

    // Channel innermost in blockIdx so the (up to) 4 blocks reading the same
    // (image, tile) region across adjacent channels land in the same wave -> L2 reuse.
    const int bid  = blockIdx.x;
    const int ch   = bid & 3;
    const int img  = (bid >> 2) & 31;
    const int tile = bid >> 7;          // 64 tiles: 4 in x, 16 in y
    const int gx0  = (tile & 3) * TW;
    const int gy0  = (tile >> 2) * TH;

    const int tid = threadIdx.x;
    const int lx  = (tid & 31) * 4;     // local output col base (0..124)
    const int oyb = (tid >> 5) * 4;     // local output row base (0..28)

    const size_t imgStride = (size_t)Hh * Ww;
    const float* srcBase = sources + ((size_t)ch * 32 + img) * imgStride;

    // ---- load src tile (+halo, zero-padded) ----
    for (int idx = tid; idx < SROWS * SCOLS; idx += NTHREADS) {
        int ry = idx / SCOLS, rx = idx - ry * SCOLS;
        int gy = gy0 + ry - 1, gx = gx0 + rx - 1;
        float v = 0.f;
        if ((unsigned)gy < (unsigned)Hh && (unsigned)gx < (unsigned)Ww)
            v = __ldg(srcBase + (size_t)gy * Ww + gx);
        s_src[ry * SW_ + rx] = v;
    }

    float acc[4][4];
    #pragma unroll
    for (int o = 0; o < 4; o++)
        #pragma unroll
        for (int c = 0; c < 4; c++) acc[o][c] = 0.f;

    // Neighbor + kernel-index table (kidx order: off=-1 first, then off=+1).
    int nnb, nbj0, nbj1, kc0, kc1;
    switch (ch) {
        case 0:  nnb = 1; nbj0 = 1; kc0 = 0;  nbj1 = 0; kc1 = 0;  break;
        case 1:  nnb = 2; nbj0 = 0; kc0 = 2;  nbj1 = 2; kc1 = 4;  break;
        case 2:  nnb = 2; nbj0 = 1; kc0 = 6;  nbj1 = 3; kc1 = 8;  break;
        default: nnb = 1; nbj0 = 2; kc0 = 10; nbj1 = 0; kc1 = 0;  break;
    }

    for (int s = 0; s < nnb; s++) {
        const int j  = (s == 0) ? nbj0 : nbj1;
        const int kc = (s == 0) ? kc0  : kc1;
        const float* nbBase = sources + ((size_t)j * 32 + img) * imgStride;

        // ---- load neighbor tile (+halo) ----
        for (int idx = tid; idx < SROWS * SCOLS; idx += NTHREADS) {
            int ry = idx / SCOLS, rx = idx - ry * SCOLS;
            int gy = gy0 + ry - 1, gx = gx0 + rx - 1;
            float v = 0.f;
            if ((unsigned)gy < (unsigned)Hh && (unsigned)gx < (unsigned)Ww)
                v = __ldg(nbBase + (size_t)gy * Ww + gx);
            s_nb[ry * SW_ + rx] = v;
        }
        __syncthreads();   // also covers s_src on first iteration

        // ---- conv pass 1: contrib = conv(nb, kA) ----
        float kk[9];
        #pragma unroll
        for (int t = 0; t < 9; t++) kk[t] = __ldg(kernels + kc * 9 + t);
        conv_accum(s_nb, kk, acc, oyb, lx);
        __syncthreads();   // all reads of s_nb done before overwrite

        // ---- elementwise inter-term, in place over the nb tile ----
        // (nb^0.5 * src)^(2/3) == cbrt(nb * src^2)
        for (int idx = tid; idx < SROWS * SCOLS; idx += NTHREADS) {
            int ry = idx / SCOLS, rx = idx - ry * SCOLS;
            int p = ry * SW_ + rx;
            float a = s_nb[p], b = s_src[p];
            s_nb[p] = fast_cbrt_nonneg(a * b * b);
        }
        __syncthreads();

        // ---- conv pass 2: inter = conv(f, kB) ----
        #pragma unroll
        for (int t = 0; t < 9; t++) kk[t] = __ldg(kernels + (kc + 1) * 9 + t);
        conv_accum(s_nb, kk, acc, oyb, lx);
        __syncthreads();   // before next neighbor overwrites s_nb
    }

    // ---- epilogue: out = src - bleed, 16B vectorized stores ----
    float* outBase = out + ((size_t)ch * 32 + img) * imgStride;
    #pragma unroll
    for (int o = 0; o < 4; o++) {
        const int gy = gy0 + oyb + o;
        const float* srow = s_src + (oyb + o + 1) * SW_ + (lx + 1);
        float4 r;
        r.x = srow[0] - acc[o][0];
        r.y = srow[1] - acc[o][1];
        r.z = srow[2] - acc[o][2];
        r.w = srow[3] - acc[o][3];
        *reinterpret_cast<float4*>(outBase + (size_t)gy * Ww + gx0 + lx) = r;
    }
}

}  // namespace

extern "C" void kernel_launch(void* const* d_in, const int* in_sizes, int n_in,
                              void* d_out, int out_size) {
    (void)in_sizes; (void)n_in; (void)out_size;
    const float* sources = (const float*)d_in[0];   // (4,32,512,512,1) fp32
    const float* kernels = (const float*)d_in[1];   // (12,3,3) fp32
    float* out = (float*)d_out;                     // (4,32,512,512,1) fp32

    // 64 tiles * 32 images * 4 channels = 8192 blocks
    bleed_kernel<<<8192, NTHREADS>>>(sources, kernels, out);
}

// round 5
// speedup vs baseline: 1.0108x; 1.0108x over previous
#include <cuda_runtime.h>

// Fused bleed-correction, v2: full-width tiles (512 x 8), shift/mask indexing,
// shfl-aligned vector loads, packed f32x2 FFMA conv.
//
// out[i] = src[i] - sum_{j in {i-1,i+1}} [ conv3x3(src[j], kA) + conv3x3(cbrt(src[j]*src[i]^2), kB) ]
// conv = cross-correlation, SAME zero pad.
//
// Tile: one block = 512 (full width) x 8 rows of one (channel, image).
// Because tiles span the full width, the x-halo is ALWAYS the image boundary
// (zero) -> no x predication anywhere. smem layout is offset-by-1 (logical col
// c at physical c+1) so conv reads are one aligned LDS.128 + LDS.64 per row
// (6 floats feed 12 taps x 3 output rows, conflict-free). Loads keep STS.128
// aligned despite the offset via a __shfl_up of the lane-boundary element.

namespace {

constexpr int Ww   = 512;
constexpr int TH   = 8;
constexpr int SROWS = TH + 2;      // 10 rows (y halo)
constexpr int SW_   = 516;         // row stride: data phys [0..512], zero pad at 513
constexpr int NTHREADS = 256;

typedef unsigned long long ull;

__device__ __forceinline__ ull pk2(float lo, float hi) {
    ull r; asm("mov.b64 %0, {%1, %2};" : "=l"(r) : "f"(lo), "f"(hi)); return r;
}
__device__ __forceinline__ void upk2(float& lo, float& hi, ull v) {
    asm("mov.b64 {%0, %1}, %2;" : "=f"(lo), "=f"(hi) : "l"(v));
}
__device__ __forceinline__ void ffma2(ull& d, ull a, ull b) {
    asm("fma.rn.f32x2 %0, %1, %2, %3;" : "=l"(d) : "l"(a), "l"(b), "l"(d));
}

__device__ __forceinline__ float cbrt_nonneg(float x) {
    // x >= 0. __powf(0, 1/3) = 0 matches zero padding.
    return __powf(x, 0.3333333333333333f);
}

// Load one full-width tile (+y halo) into smem with offset-1 layout.
// dst physical col p holds logical col p-1; logical -1 (always 0) at p=0,
// logical 511 at p=512; p=513 stays zero (pre-initialized).
__device__ __forceinline__ void load_tile(float* __restrict__ dst,
                                          const float* __restrict__ gimg,
                                          int gy0, int r0, int c4, int lane) {
    #pragma unroll
    for (int r = r0; r < SROWS; r += 2) {
        const int gy = gy0 + r - 1;
        const bool inr = (unsigned)gy < (unsigned)Ww;
        float4 v = make_float4(0.f, 0.f, 0.f, 0.f);
        if (inr) v = __ldg((const float4*)(gimg + (size_t)gy * Ww) + c4);
        // shift right by one: physical slot 4c4 gets logical col 4c4-1
        float up = __shfl_up_sync(0xffffffffu, v.w, 1);
        if (lane == 0) {
            up = 0.f;                               // c4==0: logical -1 = 0
            if (c4 != 0 && inr) up = __ldg(gimg + (size_t)gy * Ww + 4 * c4 - 1);
        }
        float* row = dst + r * SW_;
        *(float4*)(row + 4 * c4) = make_float4(up, v.x, v.y, v.z);
        if (c4 == 127) row[512] = v.w;              // logical col 511
    }
}

// Accumulate conv3x3(s, kernel K) into packed accumulators.
// Thread outputs: local rows oyb..oyb+3, cols lx..lx+3 (two f32x2 pairs/row).
__device__ __forceinline__ void conv_accum(const float* __restrict__ s,
                                           const ull K[9],
                                           ull acc[4][2],
                                           int oyb, int lx) {
    #pragma unroll
    for (int iy = 0; iy < 6; iy++) {
        const float* row = s + (oyb + iy) * SW_ + lx;   // 16B aligned
        float4 a = *(const float4*)row;                 // logical lx-1..lx+2
        float2 b = *(const float2*)(row + 4);           // logical lx+3, lx+4
        ull P0 = pk2(a.x, a.y);
        ull P1 = pk2(a.y, a.z);
        ull P2 = pk2(a.z, a.w);
        ull P3 = pk2(a.w, b.x);
        ull P4 = pk2(b.x, b.y);
        #pragma unroll
        for (int o = 0; o < 4; o++) {
            const int kr = iy - o;                      // kernel row
            if (kr >= 0 && kr < 3) {
                ffma2(acc[o][0], K[kr * 3 + 0], P0);
                ffma2(acc[o][0], K[kr * 3 + 1], P1);
                ffma2(acc[o][0], K[kr * 3 + 2], P2);
                ffma2(acc[o][1], K[kr * 3 + 0], P2);
                ffma2(acc[o][1], K[kr * 3 + 1], P3);
                ffma2(acc[o][1], K[kr * 3 + 2], P4);
            }
        }
    }
}

__global__ __launch_bounds__(NTHREADS, 4)
void bleed_kernel(const float* __restrict__ sources,
                  const float* __restrict__ kernels,
                  float* __restrict__ out)
{
    __shared__ __align__(16) float s_src[SROWS * SW_];
    __shared__ __align__(16) float s_nb [SROWS * SW_];

    // Channel innermost -> adjacent-channel blocks of the same (img, tile)
    // run in the same wave -> L2 reuse of shared source tiles.
    const int bid = blockIdx.x;
    const int ch  = bid & 3;
    const int img = (bid >> 2) & 31;
    const int gy0 = (bid >> 7) * TH;    // 64 y-tiles

    const int tid  = threadIdx.x;
    const int lane = tid & 31;
    const int c4   = tid & 127;         // float4 column index (0..127)
    const int lx   = c4 * 4;
    const int r0   = tid >> 7;          // 0 or 1
    const int oyb  = r0 * 4;            // output row base within tile

    const size_t imgStride = (size_t)Ww * Ww;
    const float* srcBase = sources + ((size_t)ch * 32 + img) * imgStride;

    // zero the phys-col-513 pad (read as the far halo by conv's LDS.64)
    if (tid < SROWS) {
        s_src[tid * SW_ + 513] = 0.f;
        s_nb [tid * SW_ + 513] = 0.f;
    }

    load_tile(s_src, srcBase, gy0, r0, c4, lane);

    ull acc[4][2];
    #pragma unroll
    for (int o = 0; o < 4; o++) { acc[o][0] = 0ull; acc[o][1] = 0ull; }

    // Neighbor + kernel-index table (reference kidx order: off=-1 then off=+1)
    int nnb, nbj0, nbj1, kc0, kc1;
    switch (ch) {
        case 0:  nnb = 1; nbj0 = 1; kc0 = 0;  nbj1 = 0; kc1 = 0;  break;
        case 1:  nnb = 2; nbj0 = 0; kc0 = 2;  nbj1 = 2; kc1 = 4;  break;
        case 2:  nnb = 2; nbj0 = 1; kc0 = 6;  nbj1 = 3; kc1 = 8;  break;
        default: nnb = 1; nbj0 = 2; kc0 = 10; nbj1 = 0; kc1 = 0;  break;
    }

    for (int s = 0; s < nnb; s++) {
        const int j  = (s == 0) ? nbj0 : nbj1;
        const int kc = (s == 0) ? kc0  : kc1;
        const float* nbBase = sources + ((size_t)j * 32 + img) * imgStride;

        load_tile(s_nb, nbBase, gy0, r0, c4, lane);
        __syncthreads();                         // covers s_src on first pass

        // conv pass 1: contrib = conv(nb, kA)
        {
            ull K[9];
            #pragma unroll
            for (int t = 0; t < 9; t++) {
                float k = __ldg(kernels + kc * 9 + t);
                K[t] = pk2(k, k);
            }
            conv_accum(s_nb, K, acc, oyb, lx);
        }
        __syncthreads();                         // all s_nb reads done

        // elementwise inter-term, in place: (nb^.5 * src)^(2/3) = cbrt(nb*src^2)
        #pragma unroll
        for (int r = r0; r < SROWS; r += 2) {
            float*       pn = s_nb  + r * SW_ + lx;
            const float* ps = s_src + r * SW_ + lx;
            float4 a = *(float4*)pn;
            float4 b = *(const float4*)ps;
            float4 f;
            f.x = cbrt_nonneg(a.x * b.x * b.x);
            f.y = cbrt_nonneg(a.y * b.y * b.y);
            f.z = cbrt_nonneg(a.z * b.z * b.z);
            f.w = cbrt_nonneg(a.w * b.w * b.w);
            *(float4*)pn = f;
            if (c4 == 127) {                     // physical col 512 (logical 511)
                float av = pn[4], bv = ps[4];
                pn[4] = cbrt_nonneg(av * bv * bv);
            }
        }
        __syncthreads();

        // conv pass 2: inter = conv(f, kB)
        {
            ull K[9];
            #pragma unroll
            for (int t = 0; t < 9; t++) {
                float k = __ldg(kernels + (kc + 1) * 9 + t);
                K[t] = pk2(k, k);
            }
            conv_accum(s_nb, K, acc, oyb, lx);
        }
        __syncthreads();                         // before next neighbor load
    }

    // epilogue: out = src - bleed (vectorized, always in range: 512 % 8 == 0)
    float* outBase = out + ((size_t)ch * 32 + img) * imgStride;
    #pragma unroll
    for (int o = 0; o < 4; o++) {
        const float* row = s_src + (oyb + o + 1) * SW_ + lx;  // phys = logical+1
        float4 a = *(const float4*)row;      // logical lx-1..lx+2
        float2 b = *(const float2*)(row + 4);
        float c0, c1, c2, c3;
        upk2(c0, c1, acc[o][0]);
        upk2(c2, c3, acc[o][1]);
        float4 r;
        r.x = a.y - c0;
        r.y = a.z - c1;
        r.z = a.w - c2;
        r.w = b.x - c3;
        const int gy = gy0 + oyb + o;
        *(float4*)(outBase + (size_t)gy * Ww + lx) = r;
    }
}

}  // namespace

extern "C" void kernel_launch(void* const* d_in, const int* in_sizes, int n_in,
                              void* d_out, int out_size) {
    (void)in_sizes; (void)n_in; (void)out_size;
    const float* sources = (const float*)d_in[0];   // (4,32,512,512,1) fp32
    const float* kernels = (const float*)d_in[1];   // (12,3,3) fp32
    float* out = (float*)d_out;                     // (4,32,512,512,1) fp32

    // 4 channels * 32 images * 64 y-tiles = 8192 blocks
    bleed_kernel<<<8192, NTHREADS>>>(sources, kernels, out);
}

// round 8
// speedup vs baseline: 1.8248x; 1.8054x over previous
#include <cuda_runtime.h>

// Fused bleed-correction, v3: single-sweep per neighbor.
//
// out[i] = src[i] - sum_{j in {i-1,i+1}} [ conv3x3(src[j], kA) + conv3x3(f_ij, kB) ]
//   with f_ij = (src[j]^0.5 * src[i])^(2/3) = cbrt(src[j] * src[i]^2)
// conv = cross-correlation, SAME zero pad.
//
// Tile: one block = 512 (full width) x 8 rows of one (channel, image).
// Full-width tiles -> x halo is always the image border (zero) -> no x predication.
// smem holds src + nb tiles in an offset-by-1 layout (logical col c at phys c+1)
// so conv reads are one aligned LDS.128 + LDS.64 per row.
//
// KEY CHANGE vs v2: the inter-term f is elementwise, so it is NEVER materialized.
// One sweep per neighbor reads each (nb,src) row pair once, computes f in
// registers, and accumulates BOTH convs into a single accumulator
// (acc += kA*nb + kB*f). This deletes the elementwise smem pass, the second
// conv's smem reads, and 2 of 3 barriers -> smem-port cycles nearly halved.

namespace {

constexpr int Ww   = 512;
constexpr int TH   = 8;
constexpr int SROWS = TH + 2;      // 10 rows (y halo)
constexpr int SW_   = 516;         // row stride: data phys [0..512], zero pad at 513
constexpr int NTHREADS = 256;

__device__ __forceinline__ float cbrt_nonneg(float x) {
    // x >= 0. lg2(0) = -inf -> ex2 -> 0, matches zero padding.
    return __powf(x, 0.3333333333333333f);
}

// Load one full-width tile (+y halo) into smem with offset-1 layout.
// phys col p holds logical col p-1; logical -1 (zero) at p=0, logical 511 at
// p=512; p=513 stays zero (pre-initialized) for the far-halo LDS.64.
__device__ __forceinline__ void load_tile(float* __restrict__ dst,
                                          const float* __restrict__ gimg,
                                          int gy0, int r0, int c4, int lane) {
    #pragma unroll
    for (int r = r0; r < SROWS; r += 2) {
        const int gy = gy0 + r - 1;
        const bool inr = (unsigned)gy < (unsigned)Ww;
        float4 v = make_float4(0.f, 0.f, 0.f, 0.f);
        if (inr) v = __ldg((const float4*)(gimg + (size_t)gy * Ww) + c4);
        // shift right by one: phys slot 4*c4 gets logical col 4*c4 - 1
        float up = __shfl_up_sync(0xffffffffu, v.w, 1);
        if (lane == 0) {
            up = 0.f;                               // c4==0: logical -1 = 0
            if (c4 != 0 && inr) up = __ldg(gimg + (size_t)gy * Ww + 4 * c4 - 1);
        }
        float* row = dst + r * SW_;
        *(float4*)(row + 4 * c4) = make_float4(up, v.x, v.y, v.z);
        if (c4 == 127) row[512] = v.w;              // logical col 511
    }
}

__global__ __launch_bounds__(NTHREADS, 4)
void bleed_kernel(const float* __restrict__ sources,
                  const float* __restrict__ kernels,
                  float* __restrict__ out)
{
    __shared__ __align__(16) float s_src[SROWS * SW_];
    __shared__ __align__(16) float s_nb [SROWS * SW_];

    // Channel innermost -> adjacent-channel blocks of the same (img, y-tile)
    // run in the same wave -> L2 reuse of shared source tiles.
    const int bid = blockIdx.x;
    const int ch  = bid & 3;
    const int img = (bid >> 2) & 31;
    const int gy0 = (bid >> 7) * TH;    // 64 y-tiles

    const int tid  = threadIdx.x;
    const int lane = tid & 31;
    const int c4   = tid & 127;         // float4 column index (0..127)
    const int lx   = c4 * 4;
    const int r0   = tid >> 7;          // 0 or 1
    const int oyb  = r0 * 4;            // output row base within tile

    const size_t imgStride = (size_t)Ww * Ww;
    const float* srcBase = sources + ((size_t)ch * 32 + img) * imgStride;

    // zero the phys-col-513 pad
    if (tid < SROWS) {
        s_src[tid * SW_ + 513] = 0.f;
        s_nb [tid * SW_ + 513] = 0.f;
    }

    load_tile(s_src, srcBase, gy0, r0, c4, lane);

    float acc[4][4];
    #pragma unroll
    for (int o = 0; o < 4; o++)
        #pragma unroll
        for (int c = 0; c < 4; c++) acc[o][c] = 0.f;

    // Neighbor + kernel-index table (reference kidx order: off=-1 then off=+1)
    int nnb, nbj0, nbj1, kc0, kc1;
    switch (ch) {
        case 0:  nnb = 1; nbj0 = 1; kc0 = 0;  nbj1 = 0; kc1 = 0;  break;
        case 1:  nnb = 2; nbj0 = 0; kc0 = 2;  nbj1 = 2; kc1 = 4;  break;
        case 2:  nnb = 2; nbj0 = 1; kc0 = 6;  nbj1 = 3; kc1 = 8;  break;
        default: nnb = 1; nbj0 = 2; kc0 = 10; nbj1 = 0; kc1 = 0;  break;
    }

    for (int s = 0; s < nnb; s++) {
        const int j  = (s == 0) ? nbj0 : nbj1;
        const int kc = (s == 0) ? kc0  : kc1;
        const float* nbBase = sources + ((size_t)j * 32 + img) * imgStride;

        load_tile(s_nb, nbBase, gy0, r0, c4, lane);

        // both conv kernels for this neighbor
        float kA[9], kB[9];
        #pragma unroll
        for (int t = 0; t < 9; t++) {
            kA[t] = __ldg(kernels + kc * 9 + t);
            kB[t] = __ldg(kernels + (kc + 1) * 9 + t);
        }

        __syncthreads();    // nb tile visible (covers s_src on first pass)

        // ---- single fused sweep: convA(nb) + convB(cbrt(nb*src^2)) ----
        #pragma unroll
        for (int iy = 0; iy < 6; iy++) {
            const float* rn = s_nb  + (oyb + iy) * SW_ + lx;  // 16B aligned
            const float* rs = s_src + (oyb + iy) * SW_ + lx;
            float4 n0 = *(const float4*)rn;
            float2 n1 = *(const float2*)(rn + 4);
            float4 s0 = *(const float4*)rs;
            float2 s1 = *(const float2*)(rs + 4);
            float n[6]  = {n0.x, n0.y, n0.z, n0.w, n1.x, n1.y};
            float sv[6] = {s0.x, s0.y, s0.z, s0.w, s1.x, s1.y};
            float f[6];
            #pragma unroll
            for (int c = 0; c < 6; c++)
                f[c] = cbrt_nonneg(n[c] * sv[c] * sv[c]);

            #pragma unroll
            for (int o = 0; o < 4; o++) {
                const int kr = iy - o;              // kernel row index
                if (kr >= 0 && kr < 3) {
                    #pragma unroll
                    for (int c = 0; c < 4; c++) {
                        float a = acc[o][c];
                        a = fmaf(kA[kr * 3 + 0], n[c + 0], a);
                        a = fmaf(kA[kr * 3 + 1], n[c + 1], a);
                        a = fmaf(kA[kr * 3 + 2], n[c + 2], a);
                        a = fmaf(kB[kr * 3 + 0], f[c + 0], a);
                        a = fmaf(kB[kr * 3 + 1], f[c + 1], a);
                        a = fmaf(kB[kr * 3 + 2], f[c + 2], a);
                        acc[o][c] = a;
                    }
                }
            }
        }

        if (s + 1 < nnb) __syncthreads();   // before next neighbor overwrites s_nb
    }

    // ---- epilogue: out = src - bleed (512 % 8 == 0 -> always in range) ----
    float* outBase = out + ((size_t)ch * 32 + img) * imgStride;
    #pragma unroll
    for (int o = 0; o < 4; o++) {
        const float* row = s_src + (oyb + o + 1) * SW_ + lx;  // phys = logical+1
        float4 a = *(const float4*)row;      // logical lx-1..lx+2
        float2 b = *(const float2*)(row + 4);
        float4 r;
        r.x = a.y - acc[o][0];
        r.y = a.z - acc[o][1];
        r.z = a.w - acc[o][2];
        r.w = b.x - acc[o][3];
        const int gy = gy0 + oyb + o;
        *(float4*)(outBase + (size_t)gy * Ww + lx) = r;
    }
}

}  // namespace

extern "C" void kernel_launch(void* const* d_in, const int* in_sizes, int n_in,
                              void* d_out, int out_size) {
    (void)in_sizes; (void)n_in; (void)out_size;
    const float* sources = (const float*)d_in[0];   // (4,32,512,512,1) fp32
    const float* kernels = (const float*)d_in[1];   // (12,3,3) fp32
    float* out = (float*)d_out;                     // (4,32,512,512,1) fp32

    // 4 channels * 32 images * 64 y-tiles = 8192 blocks
    bleed_kernel<<<8192, NTHREADS>>>(sources, kernels, out);
}